// round 13
// baseline (speedup 1.0000x reference)
#include <cuda_runtime.h>
#include <cuda_bf16.h>
#include <cstdint>

// Correlation1D band-GEMM: k16 bf16 3-pass fp32 emulation.
// R13 = R12 (m32 warps, 3-slot cp.async ring, A-direct, strength-reduced) with
// persistent multi-tile CTAs: 256 CTAs x 3 (b,h) tiles = exactly one wave at
// 2 CTAs/SM. Ring slots continue across tiles; next tile's first two chunks are
// prefetched before the current tile's epilogue (scratch moved to tile region).
// out[b,d,h,w] = (1/256)*sum_c in1[b,c,h,w]*in2pad[b,c,h,w+d-40]

#define Bn 8
#define Cn 256
#define Hn 96
#define Wn 192
#define Dn 81
#define PADn 40
#define HWn (Hn * Wn)

#define NTHREADS 192
#define KC 16
#define NCHUNK (Cn / KC)          // 16
#define BROWS 272
#define NTILE 3
#define NGRID 256                 // 256*3 = 768 = Bn*Hn

#define STROWF 196
#define STROWB (STROWF * 4)       // 784
#define STBYTES (KC * STROWB)     // 12544
#define STPAIR (2 * STBYTES)      // 25088

#define ROWB 64                   // tileB row: [hi 16ch = 32B | lo 32B]
#define TBB (BROWS * ROWB)        // 17408

#define OFF_TB0 (3 * STPAIR)                // 75264
#define OFF_TB1 (OFF_TB0 + TBB)             // 92672
#define SMEM_USED (OFF_TB1 + TBB)           // 110080
#define DYNSMEM (SMEM_USED + 1024)

#define SWX(row, koff) ((unsigned)(koff) ^ ((((unsigned)(row) >> 1) & 3u) << 4))

static __device__ __forceinline__ uint32_t smem_u32(const void* p) {
    uint32_t a;
    asm("{ .reg .u64 t; cvta.to.shared.u64 t, %1; cvt.u32.u64 %0, t; }" : "=r"(a) : "l"(p));
    return a;
}

static __device__ __forceinline__ void cp_async16(uint32_t dst, const void* src) {
    asm volatile("cp.async.cg.shared.global [%0], [%1], 16;" :: "r"(dst), "l"(src) : "memory");
}

#define MMA_BF16(a4, A, b0, b1)                                                \
    asm volatile("mma.sync.aligned.m16n8k16.row.col.f32.bf16.bf16.f32 "        \
        "{%0,%1,%2,%3}, {%4,%5,%6,%7}, {%8,%9}, {%0,%1,%2,%3};"                \
        : "+f"((a4)[0]), "+f"((a4)[1]), "+f"((a4)[2]), "+f"((a4)[3])           \
        : "r"((A)[0]), "r"((A)[1]), "r"((A)[2]), "r"((A)[3]), "r"(b0), "r"(b1))

#define LDSM_X4(r, addr)                                                       \
    asm volatile("ldmatrix.sync.aligned.m8n8.x4.shared.b16 {%0,%1,%2,%3}, [%4];" \
        : "=r"((r)[0]), "=r"((r)[1]), "=r"((r)[2]), "=r"((r)[3]) : "r"(addr))

__global__ __launch_bounds__(NTHREADS, 2)
void corr1d_pt_kernel(const float* __restrict__ in1,
                      const float* __restrict__ in2,
                      float* __restrict__ out) {
    extern __shared__ char dsm_raw[];
    const uint32_t dsm_addr = smem_u32(dsm_raw);
    const uint32_t base_u = (dsm_addr + 1023u) & ~1023u;
    char* smp = dsm_raw + (base_u - dsm_addr);

    const int tid = threadIdx.x;
    const int wid = tid >> 5;
    const int lane = tid & 31;

    // ---- cp.async per-thread constants ----
    const int iq16 = (tid % 48) * 16;
    const int ikr = tid / 48;
    const uint32_t dstoff = (uint32_t)(ikr * STROWB + iq16);

    // ---- convert per-thread static tasks (u, g, col, valid) ----
    const int cu0 = tid, cc0 = tid - PADn;
    const bool cv0 = (tid >= PADn);
    const int cu1 = (tid < 80) ? (tid + 192) : (tid - 80);
    const int cg1 = (tid < 80) ? 0 : 1;
    const int cc1 = (tid < 80) ? (tid + 152) : (tid - 120);
    const bool cv1 = (tid < 40) || (tid >= 120);
    const int cu2 = tid + 112, cc2 = tid + 72;
    const bool cv2 = (tid < 120);

    // compute constants
    const int w0 = wid * 32;
    const int b_rowoff = (lane & 7) + ((lane >> 4) & 1) * 8;
    const int b_k16 = ((lane >> 3) & 1) * 16;
    const int ad_w = w0 + (lane >> 2);
    const int ad_k = (lane & 3) * 2;

    // per-thread cp.async source pointers (updated per tile)
    const float* a_tsrc;
    const float* b_tsrc;
    auto set_tile_ptrs = [&](int g) {
        const int bb = g / Hn, hh = g % Hn;
        const size_t off = (size_t)bb * Cn * HWn + (size_t)hh * Wn + (size_t)ikr * HWn + (iq16 >> 2);
        a_tsrc = in1 + off;
        b_tsrc = in2 + off;
    };

    int isl = 0;   // ring slot for next issue (persists across tiles)
    auto issue = [&](int ch) {
        const uint32_t stA = base_u + (uint32_t)isl * STPAIR + dstoff;
        const uint32_t stB = stA + STBYTES;
        const size_t co = (size_t)ch * KC * HWn;
        const float* pa = a_tsrc + co;
        const float* pb = b_tsrc + co;
#pragma unroll
        for (int j = 0; j < 4; ++j) {
            cp_async16(stA + j * (4 * STROWB), pa + (size_t)(4 * j) * HWn);
            cp_async16(stB + j * (4 * STROWB), pb + (size_t)(4 * j) * HWn);
        }
        asm volatile("cp.async.commit_group;" ::: "memory");
        isl = (isl == 2) ? 0 : isl + 1;
    };

    auto cvtask = [&](const char* sb, char* tbp, int u, int g, int col, bool valid) {
        if (!valid) return;
        float v[8];
#pragma unroll
        for (int j = 0; j < 8; ++j)
            v[j] = *(const float*)(sb + (8 * g + j) * STROWB + 4 * col);
        unsigned hu[4], lu[4];
#pragma unroll
        for (int k = 0; k < 4; ++k) {
            __nv_bfloat162 hh = __floats2bfloat162_rn(v[2 * k], v[2 * k + 1]);
            const float r0 = v[2 * k] - __bfloat162float(hh.x);
            const float r1 = v[2 * k + 1] - __bfloat162float(hh.y);
            __nv_bfloat162 ll = __floats2bfloat162_rn(r0, r1);
            hu[k] = *(unsigned*)&hh;
            lu[k] = *(unsigned*)&ll;
        }
        char* rowp = tbp + u * ROWB;
        *(uint4*)(rowp + SWX(u, 16 * g)) = make_uint4(hu[0], hu[1], hu[2], hu[3]);
        *(uint4*)(rowp + SWX(u, 32 + 16 * g)) = make_uint4(lu[0], lu[1], lu[2], lu[3]);
    };

    auto zero_pads = [&]() {
        for (int t = tid; t < 2 * 80 * 4; t += NTHREADS) {
            const int buf = t / 320;
            const int r = (t % 320) / 4;
            const int j = t % 4;
            const int u = (r < 40) ? r : (232 + r - 40);
            ((uint4*)(smp + (buf ? OFF_TB1 : OFF_TB0) + u * ROWB))[j] = make_uint4(0, 0, 0, 0);
        }
    };

    float acc[24][4];
    uint32_t AH[2][4], AL[2][4];
    int csl = 0;   // ring slot being consumed (persists across tiles)

    // ---- prologue for tile 0 ----
    set_tile_ptrs(blockIdx.x);
    issue(0);
    issue(1);
    zero_pads();
    asm volatile("cp.async.wait_group 1;" ::: "memory");
    __syncthreads();

    for (int t = 0; t < NTILE; ++t) {
        const int g = blockIdx.x + NGRID * t;
        const int bc = g / Hn, hc = g % Hn;   // current tile coords (for epilogue)

#pragma unroll
        for (int n = 0; n < 24; ++n)
#pragma unroll
            for (int i = 0; i < 4; ++i) acc[n][i] = 0.0f;

        // ================= K loop (identical to R12) =================
        for (int i = 0; i < NCHUNK; ++i) {
            if (i + 2 < NCHUNK) issue(i + 2);

            {   // convert B(i): stageB[csl] -> tileB[i&1]
                const char* sb = smp + csl * STPAIR + STBYTES;
                char* tbp = smp + ((i & 1) ? OFF_TB1 : OFF_TB0);
                cvtask(sb, tbp, cu0, 0, cc0, cv0);
                cvtask(sb, tbp, cu1, cg1, cc1, cv1);
                cvtask(sb, tbp, cu2, 1, cc2, cv2);
            }

            if (i > 0) {   // compute chunk i-1 from tileB[(i-1)&1]
                const uint32_t tb = base_u + (((i - 1) & 1) ? OFF_TB1 : OFF_TB0);
#pragma unroll
                for (int ntp = 0; ntp < 7; ++ntp) {
                    const int ub = w0 + ntp * 16 + b_rowoff;
                    uint32_t bh[4], bl[4];
                    LDSM_X4(bh, tb + ub * ROWB + SWX(ub, b_k16));
                    LDSM_X4(bl, tb + ub * ROWB + SWX(ub, 32 + b_k16));
#pragma unroll
                    for (int t2 = 0; t2 < 2; ++t2) {
                        const int tj = ntp * 2 + t2;
                        const uint32_t b0h = bh[2 * t2], b1h = bh[2 * t2 + 1];
                        const uint32_t b0l = bl[2 * t2], b1l = bl[2 * t2 + 1];
                        if (tj < 12) {
                            float* a4 = acc[tj];
                            MMA_BF16(a4, AH[0], b0h, b1h);
                            MMA_BF16(a4, AH[0], b0l, b1l);
                            MMA_BF16(a4, AL[0], b0h, b1h);
                        }
                        if (tj >= 2) {
                            float* a4 = acc[12 + tj - 2];
                            MMA_BF16(a4, AH[1], b0h, b1h);
                            MMA_BF16(a4, AH[1], b0l, b1l);
                            MMA_BF16(a4, AL[1], b0h, b1h);
                        }
                    }
                }
            }

            {   // build A fragments for chunk i from stageA[csl]
                const char* sa = smp + csl * STPAIR;
#pragma unroll
                for (int mt = 0; mt < 2; ++mt) {
#pragma unroll
                    for (int q = 0; q < 4; ++q) {
                        const int ww = ad_w + 16 * mt + (q & 1) * 8;
                        const int kk = ad_k + (q >> 1) * 8;
                        const float f0 = *(const float*)(sa + kk * STROWB + 4 * ww);
                        const float f1 = *(const float*)(sa + (kk + 1) * STROWB + 4 * ww);
                        __nv_bfloat162 hh = __floats2bfloat162_rn(f0, f1);
                        const float r0 = f0 - __bfloat162float(hh.x);
                        const float r1 = f1 - __bfloat162float(hh.y);
                        __nv_bfloat162 ll = __floats2bfloat162_rn(r0, r1);
                        AH[mt][q] = *(uint32_t*)&hh;
                        AL[mt][q] = *(uint32_t*)&ll;
                    }
                }
            }

            if (i + 2 < NCHUNK) {
                asm volatile("cp.async.wait_group 1;" ::: "memory");
            } else {
                asm volatile("cp.async.wait_group 0;" ::: "memory");
            }
            __syncthreads();
            csl = (csl == 2) ? 0 : csl + 1;
        }

        // ---- prefetch next tile's first two chunks (overlaps tail + epilogue) ----
        if (t + 1 < NTILE) {
            set_tile_ptrs(blockIdx.x + NGRID * (t + 1));
            issue(0);
            issue(1);
        }

        // ---- tail: compute chunk NCHUNK-1 from tileB[1] ----
        {
            const uint32_t tb = base_u + OFF_TB1;   // (NCHUNK-1)&1 == 1
#pragma unroll
            for (int ntp = 0; ntp < 7; ++ntp) {
                const int ub = w0 + ntp * 16 + b_rowoff;
                uint32_t bh[4], bl[4];
                LDSM_X4(bh, tb + ub * ROWB + SWX(ub, b_k16));
                LDSM_X4(bl, tb + ub * ROWB + SWX(ub, 32 + b_k16));
#pragma unroll
                for (int t2 = 0; t2 < 2; ++t2) {
                    const int tj = ntp * 2 + t2;
                    const uint32_t b0h = bh[2 * t2], b1h = bh[2 * t2 + 1];
                    const uint32_t b0l = bl[2 * t2], b1l = bl[2 * t2 + 1];
                    if (tj < 12) {
                        float* a4 = acc[tj];
                        MMA_BF16(a4, AH[0], b0h, b1h);
                        MMA_BF16(a4, AH[0], b0l, b1l);
                        MMA_BF16(a4, AL[0], b0h, b1h);
                    }
                    if (tj >= 2) {
                        float* a4 = acc[12 + tj - 2];
                        MMA_BF16(a4, AH[1], b0h, b1h);
                        MMA_BF16(a4, AH[1], b0l, b1l);
                        MMA_BF16(a4, AL[1], b0h, b1h);
                    }
                }
            }
        }
        __syncthreads();

        // ---- epilogue: 2 d-passes through tile-region scratch (stages stay free
        //      for the in-flight next-tile DMA) ----
        float* sc = (float*)(smp + OFF_TB0);
        const float scale = 1.0f / (float)Cn;
        const int r_ = lane >> 2;
        const int col2 = (lane & 3) * 2;
#pragma unroll
        for (int p = 0; p < 2; ++p) {
            const int d0 = p * 41;
            const int dn = p ? 40 : 41;
#pragma unroll
            for (int ai = 0; ai < 24; ++ai) {
                const int mt = ai / 12;
                const int tg = (ai % 12) + 2 * mt;
#pragma unroll
                for (int half = 0; half < 2; ++half) {
                    const int mrow = 16 * mt + r_ + half * 8;
                    const int w = w0 + mrow;
#pragma unroll
                    for (int e = 0; e < 2; ++e) {
                        const int d = 8 * tg + col2 + e - mrow;
                        if (d >= d0 && d < d0 + dn) {
                            sc[(d - d0) * Wn + w] = acc[ai][half * 2 + e] * scale;
                        }
                    }
                }
            }
            __syncthreads();
            for (int tt = tid; tt < dn * (Wn / 4); tt += NTHREADS) {
                const int dd = tt / (Wn / 4);
                const int q = tt % (Wn / 4);
                const float4 v = ((const float4*)sc)[dd * (Wn / 4) + q];
                *(float4*)(out + (((size_t)bc * Dn + d0 + dd) * Hn + hc) * Wn + q * 4) = v;
            }
            __syncthreads();
        }

        // ---- restore tile pad rows (scratch clobbered them), then gate on DMA ----
        if (t + 1 < NTILE) {
            zero_pads();
            asm volatile("cp.async.wait_group 1;" ::: "memory");
            __syncthreads();
        }
    }
}

extern "C" void kernel_launch(void* const* d_in, const int* in_sizes, int n_in,
                              void* d_out, int out_size) {
    const float* in1 = (const float*)d_in[0];
    const float* in2 = (const float*)d_in[1];
    float* out = (float*)d_out;
    cudaFuncSetAttribute(corr1d_pt_kernel, cudaFuncAttributeMaxDynamicSharedMemorySize, DYNSMEM);
    corr1d_pt_kernel<<<NGRID, NTHREADS, DYNSMEM>>>(in1, in2, out);
}

// round 14
// speedup vs baseline: 1.1714x; 1.1714x over previous
#include <cuda_runtime.h>
#include <cstdint>

// Correlation1D band-GEMM, single-pass TF32 (mma.m16n8k8.tf32).
// No bf16 splits, no convert phase, no B tile: A and B fragments are built by
// conflict-free scalar LDS directly from fp32 cp.async stages (3-slot ring).
// 6 m32 warps (192 thr), one __syncthreads per 16-channel chunk.
// out[b,d,h,w] = (1/256)*sum_c in1[b,c,h,w]*in2pad[b,c,h,w+d-40]

#define Bn 8
#define Cn 256
#define Hn 96
#define Wn 192
#define Dn 81
#define PADn 40
#define HWn (Hn * Wn)

#define NTHREADS 192
#define KC 16
#define NCHUNK (Cn / KC)          // 16

#define SAROWF 196                // A stage row floats (192 used; 196%32=4 -> frag LDS conflict-free)
#define SAROWB (SAROWF * 4)       // 784
#define SABYTES (KC * SAROWB)     // 12544
#define SBROWF 280                // B stage row floats (272 used; 280%32=24 -> conflict-free)
#define SBROWB (SBROWF * 4)       // 1120
#define SBBYTES (KC * SBROWB)     // 17920
#define STPAIR (SABYTES + SBBYTES) // 30464

#define SMEM_USED (3 * STPAIR)    // 91392  (epilogue outT 62208 reuses this)
#define DYNSMEM (SMEM_USED + 1024)

static __device__ __forceinline__ uint32_t smem_u32(const void* p) {
    uint32_t a;
    asm("{ .reg .u64 t; cvta.to.shared.u64 t, %1; cvt.u32.u64 %0, t; }" : "=r"(a) : "l"(p));
    return a;
}

static __device__ __forceinline__ void cp_async16(uint32_t dst, const void* src) {
    asm volatile("cp.async.cg.shared.global [%0], [%1], 16;" :: "r"(dst), "l"(src) : "memory");
}

static __device__ __forceinline__ uint32_t f2tf32(float f) {
    uint32_t r;
    asm("cvt.rna.tf32.f32 %0, %1;" : "=r"(r) : "f"(f));
    return r;
}

#define MMA_TF32(a4, A, b0, b1)                                                \
    asm volatile("mma.sync.aligned.m16n8k8.row.col.f32.tf32.tf32.f32 "         \
        "{%0,%1,%2,%3}, {%4,%5,%6,%7}, {%8,%9}, {%0,%1,%2,%3};"                \
        : "+f"((a4)[0]), "+f"((a4)[1]), "+f"((a4)[2]), "+f"((a4)[3])           \
        : "r"((A)[0]), "r"((A)[1]), "r"((A)[2]), "r"((A)[3]), "r"(b0), "r"(b1))

__global__ __launch_bounds__(NTHREADS, 2)
void corr1d_tf_kernel(const float* __restrict__ in1,
                      const float* __restrict__ in2,
                      float* __restrict__ out) {
    extern __shared__ char dsm_raw[];
    const uint32_t dsm_addr = smem_u32(dsm_raw);
    const uint32_t base_u = (dsm_addr + 1023u) & ~1023u;
    char* smp = dsm_raw + (base_u - dsm_addr);

    const int h = blockIdx.x;
    const int b = blockIdx.y;
    const int tid = threadIdx.x;
    const int wid = tid >> 5;
    const int lane = tid & 31;

    const float* a_src = in1 + (size_t)b * Cn * HWn + (size_t)h * Wn;
    const float* b_src = in2 + (size_t)b * Cn * HWn + (size_t)h * Wn;

    // ---- cp.async per-thread constants: 8 ops/thread (4 A + 4 B rows) ----
    const int iq16 = (tid % 48) * 16;      // byte offset of 16B run within a row
    const int ikr = tid / 48;              // base k row 0..3 (k = ikr + 4j)
    const float* a_tsrc = a_src + (size_t)ikr * HWn + (iq16 >> 2);
    const float* b_tsrc = b_src + (size_t)ikr * HWn + (iq16 >> 2);
    const uint32_t a_dst0 = (uint32_t)(ikr * SAROWB + iq16);
    const uint32_t b_dst0 = (uint32_t)(ikr * SBROWB + PADn * 4 + iq16);

    // ---- zero B-stage pad cols (u<40, u in [232,272)) in all 3 ring slots ----
    for (int t = tid; t < 3 * KC * 20; t += NTHREADS) {
        const int sl = t / (KC * 20);
        const int r = (t % (KC * 20)) / 20;
        const int jj = t % 20;
        const uint32_t off = (jj < 10) ? (uint32_t)(jj * 16)
                                       : (uint32_t)(232 * 4 + (jj - 10) * 16);
        *(uint4*)(smp + sl * STPAIR + SABYTES + r * SBROWB + off) = make_uint4(0, 0, 0, 0);
    }

    float acc[24][4];
#pragma unroll
    for (int n = 0; n < 24; ++n)
#pragma unroll
        for (int i = 0; i < 4; ++i) acc[n][i] = 0.0f;

    // ---- fragment-LDS per-thread byte offsets (within a ring slot) ----
    const int w0 = wid * 32;
    // A: addr = (8s + (l&3) + dk)*SAROWB + 4*(w0 + 16*mt + (l>>2) + dm)
    const uint32_t a_fr = (uint32_t)((lane & 3) * SAROWB + 4 * (w0 + (lane >> 2)));
    // B: addr = SABYTES + (8s + (l&3) [+4])*SBROWB + 4*(u0 + (l>>2)), u0 = w0 + 8*tj
    const uint32_t b_fr = (uint32_t)(SABYTES + (lane & 3) * SBROWB + 4 * (w0 + (lane >> 2)));

    auto issue = [&](int ch, int sl) {
        const uint32_t stA = base_u + (uint32_t)sl * STPAIR + a_dst0;
        const uint32_t stB = base_u + (uint32_t)sl * STPAIR + SABYTES + b_dst0;
        const size_t co = (size_t)ch * KC * HWn;
        const float* pa = a_tsrc + co;
        const float* pb = b_tsrc + co;
#pragma unroll
        for (int j = 0; j < 4; ++j) {
            cp_async16(stA + j * (4 * SAROWB), pa + (size_t)(4 * j) * HWn);
            cp_async16(stB + j * (4 * SBROWB), pb + (size_t)(4 * j) * HWn);
        }
        asm volatile("cp.async.commit_group;" ::: "memory");
    };

    issue(0, 0);
    issue(1, 1);
    asm volatile("cp.async.wait_group 1;" ::: "memory");   // chunk 0 complete
    __syncthreads();                                        // + pad zeros visible

    int csl = 0, isl = 2;
    for (int i = 0; i < NCHUNK; ++i) {
        if (i + 2 < NCHUNK) issue(i + 2, isl);

        // ---- compute chunk i directly from stage slot csl ----
        {
            const char* sp = smp + csl * STPAIR;
#pragma unroll
            for (int s = 0; s < 2; ++s) {
                const char* spA = sp + s * (8 * SAROWB);
                const char* spB = sp + s * (8 * SBROWB);
                // A fragments for both m16 tiles (k8 slice s)
                uint32_t A0[4], A1[4];
#pragma unroll
                for (int q = 0; q < 4; ++q) {
                    const uint32_t o = a_fr + (uint32_t)((q >> 1) * (4 * SAROWB) + (q & 1) * 32);
                    A0[q] = f2tf32(*(const float*)(spA + o));
                    A1[q] = f2tf32(*(const float*)(spA + o + 64));
                }
#pragma unroll
                for (int tj = 0; tj < 14; ++tj) {
                    const uint32_t bo = b_fr + (uint32_t)(tj * 32);
                    const uint32_t b0 = f2tf32(*(const float*)(spB + bo));
                    const uint32_t b1 = f2tf32(*(const float*)(spB + bo + 4 * SBROWB));
                    if (tj < 12) MMA_TF32(acc[tj], A0, b0, b1);
                    if (tj >= 2) MMA_TF32(acc[12 + tj - 2], A1, b0, b1);
                }
            }
        }

        if (i + 2 < NCHUNK) {
            asm volatile("cp.async.wait_group 1;" ::: "memory");
        } else {
            asm volatile("cp.async.wait_group 0;" ::: "memory");
        }
        __syncthreads();   // stage(i+1) ready; all reads of slot csl done

        csl = (csl == 2) ? 0 : csl + 1;
        isl = (isl == 2) ? 0 : isl + 1;
    }

    // ---- epilogue: band extraction into smem, then coalesced store ----
    float* outT = (float*)smp;  // [81][192] f32 over the (now dead) stages
    const float scale = 1.0f / (float)Cn;
    const int r_ = lane >> 2;
    const int col2 = (lane & 3) * 2;
#pragma unroll
    for (int ai = 0; ai < 24; ++ai) {
        const int mt = ai / 12;
        const int tg = (ai % 12) + 2 * mt;    // global n8 tile index
#pragma unroll
        for (int half = 0; half < 2; ++half) {
            const int mrow = 16 * mt + r_ + half * 8;
            const int w = w0 + mrow;
#pragma unroll
            for (int e = 0; e < 2; ++e) {
                const int d = 8 * tg + col2 + e - mrow;
                if (d >= 0 && d < Dn) {
                    outT[d * Wn + w] = acc[ai][half * 2 + e] * scale;
                }
            }
        }
    }
    __syncthreads();

    for (int t = tid; t < Dn * (Wn / 4); t += NTHREADS) {
        const int d = t / (Wn / 4);
        const int q = t % (Wn / 4);
        const float4 v = ((const float4*)outT)[d * (Wn / 4) + q];
        *(float4*)(out + (((size_t)b * Dn + d) * Hn + h) * Wn + q * 4) = v;
    }
}

extern "C" void kernel_launch(void* const* d_in, const int* in_sizes, int n_in,
                              void* d_out, int out_size) {
    const float* in1 = (const float*)d_in[0];
    const float* in2 = (const float*)d_in[1];
    float* out = (float*)d_out;
    cudaFuncSetAttribute(corr1d_tf_kernel, cudaFuncAttributeMaxDynamicSharedMemorySize, DYNSMEM);
    dim3 grid(Hn, Bn);   // (96, 8)
    corr1d_tf_kernel<<<grid, NTHREADS, DYNSMEM>>>(in1, in2, out);
}